// round 15
// baseline (speedup 1.0000x reference)
#include <cuda_runtime.h>

// BQNN_hardware — row-pair SIMD (f32x2), R13: warp-parallel uniform trig.
// R13 changes vs R12 (10.7us wall, occ 29.8%, issue 48% — MUFU-heavy mix):
//   - the 11 uniform sincos (pth/pphi), previously recomputed by EVERY thread
//     (22 MUFU + LDG chains), are now computed once per warp: lanes 0..10 each
//     do ONE sincos, values broadcast via __shfl_sync at point of use.
//     MUFU instr/thread ~102 -> ~82; serial uniform-trig head removed.
//   - __launch_bounds__(128, 7): regs <= 72 -> 7 blocks/SM = 43.75% occ cap.

#define NPAIR 15
#define TPB 128
#define RPW 64              // rows per warp (2 per lane)
#define RPB (TPB * 2)       // rows per block

typedef unsigned long long u64;

__device__ __forceinline__ u64 pk2(float a, float b) {
    u64 r; asm("mov.b64 %0,{%1,%2};" : "=l"(r) : "f"(a), "f"(b)); return r;
}
__device__ __forceinline__ void up2(u64 v, float& a, float& b) {
    asm("mov.b64 {%0,%1},%2;" : "=f"(a), "=f"(b) : "l"(v));
}
__device__ __forceinline__ u64 f2mul(u64 a, u64 b) {
    u64 r; asm("mul.rn.f32x2 %0,%1,%2;" : "=l"(r) : "l"(a), "l"(b)); return r;
}
__device__ __forceinline__ u64 f2fma(u64 a, u64 b, u64 c) {
    u64 r; asm("fma.rn.f32x2 %0,%1,%2,%3;" : "=l"(r) : "l"(a), "l"(b), "l"(c)); return r;
}
__device__ __forceinline__ u64 f2add(u64 a, u64 b) {
    u64 r; asm("add.rn.f32x2 %0,%1,%2;" : "=l"(r) : "l"(a), "l"(b)); return r;
}
__device__ __forceinline__ u64 f2neg(u64 a) { return a ^ 0x8000000080000000ull; }
__device__ __forceinline__ float rcp_fast(float x) {
    float r; asm("rcp.approx.f32 %0,%1;" : "=f"(r) : "f"(x)); return r;
}
__device__ __forceinline__ float sqrt_fast(float x) {
    float r; asm("sqrt.approx.f32 %0,%1;" : "=f"(r) : "f"(x)); return r;
}

#define USHFL(v, l) __shfl_sync(0xffffffffu, (v), (l))
// broadcast lane value into both f32x2 lanes
__device__ __forceinline__ u64 bshfl(float v, int l) {
    float t = USHFL(v, l);
    return pk2(t, t);
}

// ---- rotation micro-kernels (operands packed over 2 rows) ----
__device__ __forceinline__ void rot_full(u64& vix, u64& viy, u64& vjx, u64& vjy,
                                         u64 ct, u64 st, u64 nst,
                                         u64 cp, u64 sp, u64 nsp) {
    u64 wx = f2fma(cp, vix, f2mul(nsp, viy));
    u64 wy = f2fma(cp, viy, f2mul(sp, vix));
    u64 nix = f2fma(ct, wx, f2mul(nst, vjx));
    u64 niy = f2fma(ct, wy, f2mul(nst, vjy));
    vjx = f2fma(st, wx, f2mul(ct, vjx));
    vjy = f2fma(st, wy, f2mul(ct, vjy));
    vix = nix; viy = niy;
}
__device__ __forceinline__ void rot_vireal(u64& vix, u64& viy, u64& vjx, u64& vjy,
                                           u64 ct, u64 st, u64 nst,
                                           u64 cp, u64 sp) {
    u64 wx = f2mul(cp, vix);
    u64 wy = f2mul(sp, vix);
    vix = f2fma(ct, wx, f2mul(nst, vjx));
    viy = f2fma(ct, wy, f2mul(nst, vjy));
    vjx = f2fma(st, wx, f2mul(ct, vjx));
    vjy = f2fma(st, wy, f2mul(ct, vjy));
}
__device__ __forceinline__ void rot_vjzero(u64& vix, u64& viy, u64& vjx, u64& vjy,
                                           u64 ct, u64 st, u64 cp, u64 sp, u64 nsp) {
    u64 wx = f2fma(cp, vix, f2mul(nsp, viy));
    u64 wy = f2fma(cp, viy, f2mul(sp, vix));
    vix = f2mul(ct, wx); viy = f2mul(ct, wy);
    vjx = f2mul(st, wx); vjy = f2mul(st, wy);
}
__device__ __forceinline__ void rot_vireal_vjzero(u64& vix, u64& viy, u64& vjx, u64& vjy,
                                                  u64 ct, u64 st, u64 cp, u64 sp) {
    u64 wx = f2mul(cp, vix);
    u64 wy = f2mul(sp, vix);
    vix = f2mul(ct, wx); viy = f2mul(ct, wy);
    vjx = f2mul(st, wx); vjy = f2mul(st, wy);
}
__device__ __forceinline__ void rot_vireal_vjreal(u64& vix, u64& viy, u64& vjx, u64& vjy,
                                                  u64 ct, u64 st, u64 nst,
                                                  u64 cp, u64 sp) {
    u64 wx = f2mul(cp, vix);
    u64 wy = f2mul(sp, vix);
    vix = f2fma(ct, wx, f2mul(nst, vjx));
    viy = f2mul(ct, wy);
    u64 t = f2mul(ct, vjx);
    vjx = f2fma(st, wx, t);
    vjy = f2mul(st, wy);
}

__global__ __launch_bounds__(TPB, 7)
void bqnn_kernel(const float* __restrict__ x,
                 const float* __restrict__ pphi,
                 const float* __restrict__ pth,
                 const float* __restrict__ kin,
                 const float* __restrict__ bin,
                 float* __restrict__ out,
                 int B)
{
    __shared__ __align__(16) float s_out[RPB * NPAIR];  // 15360 B, warp-sliced

    const int tid  = threadIdx.x;
    const int lane = tid & 31;
    const int wid  = tid >> 5;
    const int wbase = blockIdx.x * RPB + wid * RPW;     // first row of this warp
    const int rowA = wbase + lane;
    const int rowB = rowA + 32;

    // ---- warp-parallel uniform trig: lanes 0..10 own one param angle each ----
    // lane 0: pth0 | 1: pth2 | 2: pth3 | 3..6: pth4..7 | 7..10: pphi0..3
    // (pth1 provably drops out of the folded initial state)
    float s_l, c_l;
    {
        float ang = 0.f;
        if      (lane == 0) ang = __ldg(pth + 0);
        else if (lane == 1) ang = __ldg(pth + 2);
        else if (lane == 2) ang = __ldg(pth + 3);
        else if (lane < 7)  ang = __ldg(pth + lane + 1);   // pth4..7
        else if (lane < 11) ang = __ldg(pphi + lane - 7);  // pphi0..3
        __sincosf(ang, &s_l, &c_l);
    }

    // ---- load raw inputs for both rows ----
    float xA[12], xB[12];
    {
        float4 z = make_float4(0.f, 0.f, 0.f, 0.f);
        float4 a0 = z, a1 = z, a2 = z, b0 = z, b1 = z, b2 = z;
        if (rowA < B) {
            const float4* p = reinterpret_cast<const float4*>(x + (size_t)rowA * 12);
            a0 = p[0]; a1 = p[1]; a2 = p[2];
        }
        if (rowB < B) {
            const float4* p = reinterpret_cast<const float4*>(x + (size_t)rowB * 12);
            b0 = p[0]; b1 = p[1]; b2 = p[2];
        }
        xA[0]=a0.x; xA[1]=a0.y; xA[2]=a0.z; xA[3]=a0.w;
        xA[4]=a1.x; xA[5]=a1.y; xA[6]=a1.z; xA[7]=a1.w;
        xA[8]=a2.x; xA[9]=a2.y; xA[10]=a2.z; xA[11]=a2.w;
        xB[0]=b0.x; xB[1]=b0.y; xB[2]=b0.z; xB[3]=b0.w;
        xB[4]=b1.x; xB[5]=b1.y; xB[6]=b1.z; xB[7]=b1.w;
        xB[8]=b2.x; xB[9]=b2.y; xB[10]=b2.z; xB[11]=b2.w;
    }

    // ---- packed state: columns 0 and 3 of U, 2 rows per lane ----
    // initial state (k0..k3 folded, phi=0, basis vectors)
    u64 aX[6], aY[6], bX[6], bY[6];
    #pragma unroll
    for (int i = 0; i < 6; i++) { aX[i]=0; aY[i]=0; bX[i]=0; bY[i]=0; }
    {
        float c0 = USHFL(c_l, 0), s0 = USHFL(s_l, 0);
        float c2p = USHFL(c_l, 1), s2p = USHFL(s_l, 1);
        float v1 = c2p * s0, v2 = s2p * s0;
        aX[0] = pk2(c0, c0); aX[1] = pk2(v1, v1); aX[2] = pk2(v2, v2);
        bX[3] = bshfl(c_l, 2); bX[4] = bshfl(s_l, 2);
    }

    // ---- phase A: sincos of xs0..xs5 ----
    u64 S[6], C[6];
    #pragma unroll
    for (int i = 0; i < 6; i++) {
        float vA = fmaf(xA[i], __ldg(kin + i), __ldg(bin + i));
        float vB = fmaf(xB[i], __ldg(kin + i), __ldg(bin + i));
        float sA, cA, sB, cB;
        __sincosf(vA, &sA, &cA);
        __sincosf(vB, &sB, &cB);
        S[i] = pk2(sA, sB); C[i] = pk2(cA, cB);
    }
    {
        u64 NS3 = f2neg(S[3]);
        u64 NS4 = f2neg(S[4]);
        // k4: ROT(0,1) th=xs3 ph=xs0 — va: real/real; vb untouched
        rot_vireal_vjreal(aX[0], aY[0], aX[1], aY[1], C[3], S[3], NS3, C[0], S[0]);
        // k5: ROT(2,3) th=xs4 ph=xs1 — va: real/zero; vb: zero/real
        rot_vireal_vjzero(aX[2], aY[2], aX[3], aY[3], C[4], S[4], C[1], S[1]);
        bX[2] = f2mul(NS4, bX[3]);
        bX[3] = f2mul(C[4], bX[3]);
        // k6: ROT(4,5) th=xs5 ph=xs2 — va untouched; vb: real/zero
        rot_vireal_vjzero(bX[4], bY[4], bX[5], bY[5], C[5], S[5], C[2], S[2]);
    }
    // k7: ROT(1,2) uniform u=0 — va full; vb: zero/real
    {
        u64 ct = bshfl(c_l, 3), st = bshfl(s_l, 3), nst = f2neg(st);
        u64 cp = bshfl(c_l, 7), sp = bshfl(s_l, 7), nsp = f2neg(sp);
        rot_full(aX[1], aY[1], aX[2], aY[2], ct, st, nst, cp, sp, nsp);
        bX[1] = f2mul(nst, bX[2]);
        bX[2] = f2mul(ct, bX[2]);
    }
    // k8: ROT(3,4) uniform u=1 — va: complex/zero; vb: real/complex
    {
        u64 ct = bshfl(c_l, 4), st = bshfl(s_l, 4), nst = f2neg(st);
        u64 cp = bshfl(c_l, 8), sp = bshfl(s_l, 8), nsp = f2neg(sp);
        rot_vjzero(aX[3], aY[3], aX[4], aY[4], ct, st, cp, sp, nsp);
        rot_vireal(bX[3], bY[3], bX[4], bY[4], ct, st, nst, cp, sp);
    }

    // ---- phase B: sincos of xs6..xs11 (index i ↔ xs[6+i]) ----
    #pragma unroll
    for (int i = 0; i < 6; i++) {
        float vA = fmaf(xA[6 + i], __ldg(kin + 6 + i), __ldg(bin + 6 + i));
        float vB = fmaf(xB[6 + i], __ldg(kin + 6 + i), __ldg(bin + 6 + i));
        float sA, cA, sB, cB;
        __sincosf(vA, &sA, &cA);
        __sincosf(vB, &sB, &cB);
        S[i] = pk2(sA, sB); C[i] = pk2(cA, cB);
    }
    {
        u64 NS9  = f2neg(S[3]);
        u64 NS10 = f2neg(S[4]);
        u64 NS11 = f2neg(S[5]);
        u64 NSP6 = f2neg(S[0]);
        u64 NSP7 = f2neg(S[1]);
        u64 NSP8 = f2neg(S[2]);
        // k9: ROT(0,1) th=xs9 ph=xs6 — va full; vb: zero/real
        rot_full(aX[0], aY[0], aX[1], aY[1], C[3], S[3], NS9, C[0], S[0], NSP6);
        bX[0] = f2mul(NS9, bX[1]);
        bX[1] = f2mul(C[3], bX[1]);
        // k10: ROT(2,3) th=xs10 ph=xs7 — va full; vb: real/complex
        rot_full(aX[2], aY[2], aX[3], aY[3], C[4], S[4], NS10, C[1], S[1], NSP7);
        rot_vireal(bX[2], bY[2], bX[3], bY[3], C[4], S[4], NS10, C[1], S[1]);
        // k11: ROT(4,5) th=xs11 ph=xs8 — va: complex/zero; vb full
        rot_vjzero(aX[4], aY[4], aX[5], aY[5], C[5], S[5], C[2], S[2], NSP8);
        rot_full(bX[4], bY[4], bX[5], bY[5], C[5], S[5], NS11, C[2], S[2], NSP8);
    }
    // k12: ROT(1,2) uniform u=2 — va full; vb: real/complex
    {
        u64 ct = bshfl(c_l, 5), st = bshfl(s_l, 5), nst = f2neg(st);
        u64 cp = bshfl(c_l, 9), sp = bshfl(s_l, 9), nsp = f2neg(sp);
        rot_full(aX[1], aY[1], aX[2], aY[2], ct, st, nst, cp, sp, nsp);
        rot_vireal(bX[1], bY[1], bX[2], bY[2], ct, st, nst, cp, sp);
    }
    // k13: ROT(3,4) uniform u=3 — both full
    {
        u64 ct = bshfl(c_l, 6), st = bshfl(s_l, 6), nst = f2neg(st);
        u64 cp = bshfl(c_l, 10), sp = bshfl(s_l, 10), nsp = f2neg(sp);
        rot_full(aX[3], aY[3], aX[4], aY[4], ct, st, nst, cp, sp, nsp);
        rot_full(bX[3], bY[3], bX[4], bY[4], ct, st, nst, cp, sp, nsp);
    }
    // final state: everything complex except bY[0] == 0 (exploited below)

    // ---- 15 pair amplitudes (packed): amp = a_i*b_j + a_j*b_i ----
    const int OA[NPAIR] = {0,0,0,0,0,1,1,1,1,2,2,2,3,3,4};
    const int OB[NPAIR] = {1,2,3,4,5,2,3,4,5,3,4,5,4,5,5};

    u64 m2[NPAIR];
    u64 acc0 = 0, acc1 = 0, acc2 = 0;
    #pragma unroll
    for (int p = 0; p < NPAIR; p++) {
        const int i = OA[p], j = OB[p];
        u64 ax = f2mul(aX[i], bX[j]);
        ax = f2fma(f2neg(aY[i]), bY[j], ax);
        ax = f2fma(aX[j], bX[i], ax);
        if (i != 0) ax = f2fma(f2neg(aY[j]), bY[i], ax);   // bY[0] == 0
        u64 ay = f2mul(aX[i], bY[j]);
        ay = f2fma(aY[i], bX[j], ay);
        if (i != 0) ay = f2fma(aX[j], bY[i], ay);          // bY[0] == 0
        ay = f2fma(aY[j], bX[i], ay);
        m2[p] = f2fma(ay, ay, f2mul(ax, ax));
        if      (p % 3 == 0) acc0 = f2add(acc0, m2[p]);
        else if (p % 3 == 1) acc1 = f2add(acc1, m2[p]);
        else                 acc2 = f2add(acc2, m2[p]);
    }
    u64 s2 = f2add(f2add(acc0, acc1), acc2);

    // ---- normalize + abs, staged to this warp's smem slice ----
    {
        float sA, sB;
        up2(s2, sA, sB);
        float tA = rcp_fast(fmaxf(sA, 1e-24f));
        float tB = rcp_fast(fmaxf(sB, 1e-24f));
        u64 T = pk2(tA, tB);
        float* soA = s_out + (wid * RPW + lane) * NPAIR;
        float* soB = soA + 32 * NPAIR;
        #pragma unroll
        for (int p = 0; p < NPAIR; p++) {
            u64 u = f2mul(m2[p], T);
            float uA, uB;
            up2(u, uA, uB);
            soA[p] = sqrt_fast(uA);
            soB[p] = sqrt_fast(uB);
        }
    }
    __syncwarp();

    // ---- warp-private coalesced float4 writeback (64 rows = 960 floats) ----
    {
        int rows_here = B - wbase;
        if (rows_here > 0) {
            if (rows_here > RPW) rows_here = RPW;
            const int total = rows_here * NPAIR;
            const int nvec = total >> 2;
            float4* og = reinterpret_cast<float4*>(out + (size_t)wbase * NPAIR);
            const float* ss = s_out + wid * RPW * NPAIR;
            const float4* sg = reinterpret_cast<const float4*>(ss);
            for (int v = lane; v < nvec; v += 32)
                og[v] = sg[v];
            for (int e = (nvec << 2) + lane; e < total; e += 32)
                out[(size_t)wbase * NPAIR + e] = ss[e];
        }
    }
}

extern "C" void kernel_launch(void* const* d_in, const int* in_sizes, int n_in,
                              void* d_out, int out_size)
{
    const float* x    = (const float*)d_in[0];
    const float* pphi = (const float*)d_in[1];
    const float* pth  = (const float*)d_in[2];
    const float* kin  = (const float*)d_in[3];
    const float* bin  = (const float*)d_in[4];
    float* out = (float*)d_out;

    int B = in_sizes[0] / 12;
    int blocks = (B + RPB - 1) / RPB;
    bqnn_kernel<<<blocks, TPB>>>(x, pphi, pth, kin, bin, out, B);
}

// round 16
// speedup vs baseline: 1.0269x; 1.0269x over previous
#include <cuda_runtime.h>

// BQNN_hardware — row-pair SIMD (f32x2), R16: single-wave + guard-free path.
// Base = R12 (best profiled 9.66us): point-of-use uniform trig, warp-private
// staging/writeback. Changes:
//   - __launch_bounds__(128, 7): 148*7=1036 >= 1024 blocks -> the whole grid
//     is resident in ONE wave (no wave-2 tail). Requires regs <= 72.
//   - q2 (xs8..11) load deferred past phase-A sincos: -8 peak live regs,
//     latency still hidden behind phase-A rotation math.
//   - template<bool GUARD>: B % 256 == 0 launches a guard-free kernel with a
//     fully unrolled float4 writeback (no loop overhead, no predicates).

#define NPAIR 15
#define TPB 128
#define RPW 64              // rows per warp (2 per lane)
#define RPB (TPB * 2)       // rows per block

typedef unsigned long long u64;

__device__ __forceinline__ u64 pk2(float a, float b) {
    u64 r; asm("mov.b64 %0,{%1,%2};" : "=l"(r) : "f"(a), "f"(b)); return r;
}
__device__ __forceinline__ void up2(u64 v, float& a, float& b) {
    asm("mov.b64 {%0,%1},%2;" : "=f"(a), "=f"(b) : "l"(v));
}
__device__ __forceinline__ u64 f2mul(u64 a, u64 b) {
    u64 r; asm("mul.rn.f32x2 %0,%1,%2;" : "=l"(r) : "l"(a), "l"(b)); return r;
}
__device__ __forceinline__ u64 f2fma(u64 a, u64 b, u64 c) {
    u64 r; asm("fma.rn.f32x2 %0,%1,%2,%3;" : "=l"(r) : "l"(a), "l"(b), "l"(c)); return r;
}
__device__ __forceinline__ u64 f2add(u64 a, u64 b) {
    u64 r; asm("add.rn.f32x2 %0,%1,%2;" : "=l"(r) : "l"(a), "l"(b)); return r;
}
__device__ __forceinline__ u64 f2neg(u64 a) { return a ^ 0x8000000080000000ull; }
__device__ __forceinline__ float rcp_fast(float x) {
    float r; asm("rcp.approx.f32 %0,%1;" : "=f"(r) : "f"(x)); return r;
}
__device__ __forceinline__ float sqrt_fast(float x) {
    float r; asm("sqrt.approx.f32 %0,%1;" : "=f"(r) : "f"(x)); return r;
}

// ---- rotation micro-kernels (operands packed over 2 rows) ----
__device__ __forceinline__ void rot_full(u64& vix, u64& viy, u64& vjx, u64& vjy,
                                         u64 ct, u64 st, u64 nst,
                                         u64 cp, u64 sp, u64 nsp) {
    u64 wx = f2fma(cp, vix, f2mul(nsp, viy));
    u64 wy = f2fma(cp, viy, f2mul(sp, vix));
    u64 nix = f2fma(ct, wx, f2mul(nst, vjx));
    u64 niy = f2fma(ct, wy, f2mul(nst, vjy));
    vjx = f2fma(st, wx, f2mul(ct, vjx));
    vjy = f2fma(st, wy, f2mul(ct, vjy));
    vix = nix; viy = niy;
}
__device__ __forceinline__ void rot_vireal(u64& vix, u64& viy, u64& vjx, u64& vjy,
                                           u64 ct, u64 st, u64 nst,
                                           u64 cp, u64 sp) {
    u64 wx = f2mul(cp, vix);
    u64 wy = f2mul(sp, vix);
    vix = f2fma(ct, wx, f2mul(nst, vjx));
    viy = f2fma(ct, wy, f2mul(nst, vjy));
    vjx = f2fma(st, wx, f2mul(ct, vjx));
    vjy = f2fma(st, wy, f2mul(ct, vjy));
}
__device__ __forceinline__ void rot_vjzero(u64& vix, u64& viy, u64& vjx, u64& vjy,
                                           u64 ct, u64 st, u64 cp, u64 sp, u64 nsp) {
    u64 wx = f2fma(cp, vix, f2mul(nsp, viy));
    u64 wy = f2fma(cp, viy, f2mul(sp, vix));
    vix = f2mul(ct, wx); viy = f2mul(ct, wy);
    vjx = f2mul(st, wx); vjy = f2mul(st, wy);
}
__device__ __forceinline__ void rot_vireal_vjzero(u64& vix, u64& viy, u64& vjx, u64& vjy,
                                                  u64 ct, u64 st, u64 cp, u64 sp) {
    u64 wx = f2mul(cp, vix);
    u64 wy = f2mul(sp, vix);
    vix = f2mul(ct, wx); viy = f2mul(ct, wy);
    vjx = f2mul(st, wx); vjy = f2mul(st, wy);
}
__device__ __forceinline__ void rot_vireal_vjreal(u64& vix, u64& viy, u64& vjx, u64& vjy,
                                                  u64 ct, u64 st, u64 nst,
                                                  u64 cp, u64 sp) {
    u64 wx = f2mul(cp, vix);
    u64 wy = f2mul(sp, vix);
    vix = f2fma(ct, wx, f2mul(nst, vjx));
    viy = f2mul(ct, wy);
    u64 t = f2mul(ct, vjx);
    vjx = f2fma(st, wx, t);
    vjy = f2mul(st, wy);
}

// uniform rotation trig, computed at point-of-use (short live ranges)
__device__ __forceinline__ void urot_vals(const float* __restrict__ pth,
                                          const float* __restrict__ pphi, int u,
                                          u64& ct, u64& st, u64& nst,
                                          u64& cp, u64& sp, u64& nsp) {
    float s, c, s2, c2;
    __sincosf(__ldg(pth + 4 + u), &s, &c);
    __sincosf(__ldg(pphi + u),    &s2, &c2);
    ct = pk2(c, c);  st = pk2(s, s);   nst = f2neg(st);
    cp = pk2(c2, c2); sp = pk2(s2, s2); nsp = f2neg(sp);
}

template <bool GUARD>
__global__ __launch_bounds__(TPB, 7)
void bqnn_kernel(const float* __restrict__ x,
                 const float* __restrict__ pphi,
                 const float* __restrict__ pth,
                 const float* __restrict__ kin,
                 const float* __restrict__ bin,
                 float* __restrict__ out,
                 int B)
{
    __shared__ __align__(16) float s_out[RPB * NPAIR];  // 15360 B, warp-sliced

    const int tid  = threadIdx.x;
    const int lane = tid & 31;
    const int wid  = tid >> 5;
    const int wbase = blockIdx.x * RPB + wid * RPW;     // first row of this warp
    const int rowA = wbase + lane;
    const int rowB = rowA + 32;

    // ---- load q0,q1 (xs0..7) for both rows; q2 deferred ----
    const float4* pA = reinterpret_cast<const float4*>(x + (size_t)rowA * 12);
    const float4* pB = reinterpret_cast<const float4*>(x + (size_t)rowB * 12);
    float4 a0, a1, b0, b1;
    if (GUARD) {
        float4 z = make_float4(0.f, 0.f, 0.f, 0.f);
        a0 = a1 = b0 = b1 = z;
        if (rowA < B) { a0 = pA[0]; a1 = pA[1]; }
        if (rowB < B) { b0 = pB[0]; b1 = pB[1]; }
    } else {
        a0 = pA[0]; a1 = pA[1];
        b0 = pB[0]; b1 = pB[1];
    }

    // ---- packed state: columns 0 and 3 of U, 2 rows per lane ----
    // initial state (k0..k3 folded, phi=0, basis vectors); pth1 drops out.
    u64 aX[6], aY[6], bX[6], bY[6];
    #pragma unroll
    for (int i = 0; i < 6; i++) { aX[i]=0; aY[i]=0; bX[i]=0; bY[i]=0; }
    {
        float s0, c0, s2p, c2p, s3p, c3p;
        __sincosf(__ldg(pth + 0), &s0,  &c0);
        __sincosf(__ldg(pth + 2), &s2p, &c2p);
        __sincosf(__ldg(pth + 3), &s3p, &c3p);
        float v1 = c2p * s0, v2 = s2p * s0;
        aX[0] = pk2(c0, c0); aX[1] = pk2(v1, v1); aX[2] = pk2(v2, v2);
        bX[3] = pk2(c3p, c3p); bX[4] = pk2(s3p, s3p);
    }

    // ---- phase A: sincos of xs0..xs5 (q0 + q1.xy) ----
    u64 S[6], C[6];
    {
        float rawA[6] = {a0.x, a0.y, a0.z, a0.w, a1.x, a1.y};
        float rawB[6] = {b0.x, b0.y, b0.z, b0.w, b1.x, b1.y};
        #pragma unroll
        for (int i = 0; i < 6; i++) {
            float vA = fmaf(rawA[i], __ldg(kin + i), __ldg(bin + i));
            float vB = fmaf(rawB[i], __ldg(kin + i), __ldg(bin + i));
            float sA, cA, sB, cB;
            __sincosf(vA, &sA, &cA);
            __sincosf(vB, &sB, &cB);
            S[i] = pk2(sA, sB); C[i] = pk2(cA, cB);
        }
    }

    // ---- deferred q2 load (xs8..11): issued here, consumed in phase B ----
    float4 a2, b2;
    if (GUARD) {
        float4 z = make_float4(0.f, 0.f, 0.f, 0.f);
        a2 = b2 = z;
        if (rowA < B) a2 = pA[2];
        if (rowB < B) b2 = pB[2];
    } else {
        a2 = pA[2];
        b2 = pB[2];
    }

    {
        u64 NS3 = f2neg(S[3]);
        u64 NS4 = f2neg(S[4]);
        // k4: ROT(0,1) th=xs3 ph=xs0 — va: real/real; vb untouched
        rot_vireal_vjreal(aX[0], aY[0], aX[1], aY[1], C[3], S[3], NS3, C[0], S[0]);
        // k5: ROT(2,3) th=xs4 ph=xs1 — va: real/zero; vb: zero/real
        rot_vireal_vjzero(aX[2], aY[2], aX[3], aY[3], C[4], S[4], C[1], S[1]);
        bX[2] = f2mul(NS4, bX[3]);
        bX[3] = f2mul(C[4], bX[3]);
        // k6: ROT(4,5) th=xs5 ph=xs2 — va untouched; vb: real/zero
        rot_vireal_vjzero(bX[4], bY[4], bX[5], bY[5], C[5], S[5], C[2], S[2]);
    }
    // k7: ROT(1,2) uniform u=0 — va full; vb: zero/real
    {
        u64 ct, st, nst, cp, sp, nsp;
        urot_vals(pth, pphi, 0, ct, st, nst, cp, sp, nsp);
        rot_full(aX[1], aY[1], aX[2], aY[2], ct, st, nst, cp, sp, nsp);
        bX[1] = f2mul(nst, bX[2]);
        bX[2] = f2mul(ct, bX[2]);
    }
    // k8: ROT(3,4) uniform u=1 — va: complex/zero; vb: real/complex
    {
        u64 ct, st, nst, cp, sp, nsp;
        urot_vals(pth, pphi, 1, ct, st, nst, cp, sp, nsp);
        rot_vjzero(aX[3], aY[3], aX[4], aY[4], ct, st, cp, sp, nsp);
        rot_vireal(bX[3], bY[3], bX[4], bY[4], ct, st, nst, cp, sp);
    }

    // ---- phase B: sincos of xs6..xs11 (q1.zw + q2); index i ↔ xs[6+i] ----
    {
        float rawA[6] = {a1.z, a1.w, a2.x, a2.y, a2.z, a2.w};
        float rawB[6] = {b1.z, b1.w, b2.x, b2.y, b2.z, b2.w};
        #pragma unroll
        for (int i = 0; i < 6; i++) {
            float vA = fmaf(rawA[i], __ldg(kin + 6 + i), __ldg(bin + 6 + i));
            float vB = fmaf(rawB[i], __ldg(kin + 6 + i), __ldg(bin + 6 + i));
            float sA, cA, sB, cB;
            __sincosf(vA, &sA, &cA);
            __sincosf(vB, &sB, &cB);
            S[i] = pk2(sA, sB); C[i] = pk2(cA, cB);
        }
    }
    {
        u64 NS9  = f2neg(S[3]);
        u64 NS10 = f2neg(S[4]);
        u64 NS11 = f2neg(S[5]);
        u64 NSP6 = f2neg(S[0]);
        u64 NSP7 = f2neg(S[1]);
        u64 NSP8 = f2neg(S[2]);
        // k9: ROT(0,1) th=xs9 ph=xs6 — va full; vb: zero/real
        rot_full(aX[0], aY[0], aX[1], aY[1], C[3], S[3], NS9, C[0], S[0], NSP6);
        bX[0] = f2mul(NS9, bX[1]);
        bX[1] = f2mul(C[3], bX[1]);
        // k10: ROT(2,3) th=xs10 ph=xs7 — va full; vb: real/complex
        rot_full(aX[2], aY[2], aX[3], aY[3], C[4], S[4], NS10, C[1], S[1], NSP7);
        rot_vireal(bX[2], bY[2], bX[3], bY[3], C[4], S[4], NS10, C[1], S[1]);
        // k11: ROT(4,5) th=xs11 ph=xs8 — va: complex/zero; vb full
        rot_vjzero(aX[4], aY[4], aX[5], aY[5], C[5], S[5], C[2], S[2], NSP8);
        rot_full(bX[4], bY[4], bX[5], bY[5], C[5], S[5], NS11, C[2], S[2], NSP8);
    }
    // k12: ROT(1,2) uniform u=2 — va full; vb: real/complex
    {
        u64 ct, st, nst, cp, sp, nsp;
        urot_vals(pth, pphi, 2, ct, st, nst, cp, sp, nsp);
        rot_full(aX[1], aY[1], aX[2], aY[2], ct, st, nst, cp, sp, nsp);
        rot_vireal(bX[1], bY[1], bX[2], bY[2], ct, st, nst, cp, sp);
    }
    // k13: ROT(3,4) uniform u=3 — both full
    {
        u64 ct, st, nst, cp, sp, nsp;
        urot_vals(pth, pphi, 3, ct, st, nst, cp, sp, nsp);
        rot_full(aX[3], aY[3], aX[4], aY[4], ct, st, nst, cp, sp, nsp);
        rot_full(bX[3], bY[3], bX[4], bY[4], ct, st, nst, cp, sp, nsp);
    }
    // final state: everything complex except bY[0] == 0 (exploited below)

    // ---- 15 pair amplitudes (packed): amp = a_i*b_j + a_j*b_i ----
    const int OA[NPAIR] = {0,0,0,0,0,1,1,1,1,2,2,2,3,3,4};
    const int OB[NPAIR] = {1,2,3,4,5,2,3,4,5,3,4,5,4,5,5};

    u64 m2[NPAIR];
    u64 acc0 = 0, acc1 = 0, acc2 = 0;
    #pragma unroll
    for (int p = 0; p < NPAIR; p++) {
        const int i = OA[p], j = OB[p];
        u64 ax = f2mul(aX[i], bX[j]);
        ax = f2fma(f2neg(aY[i]), bY[j], ax);
        ax = f2fma(aX[j], bX[i], ax);
        if (i != 0) ax = f2fma(f2neg(aY[j]), bY[i], ax);   // bY[0] == 0
        u64 ay = f2mul(aX[i], bY[j]);
        ay = f2fma(aY[i], bX[j], ay);
        if (i != 0) ay = f2fma(aX[j], bY[i], ay);          // bY[0] == 0
        ay = f2fma(aY[j], bX[i], ay);
        m2[p] = f2fma(ay, ay, f2mul(ax, ax));
        if      (p % 3 == 0) acc0 = f2add(acc0, m2[p]);
        else if (p % 3 == 1) acc1 = f2add(acc1, m2[p]);
        else                 acc2 = f2add(acc2, m2[p]);
    }
    u64 s2 = f2add(f2add(acc0, acc1), acc2);

    // ---- normalize + abs, staged to this warp's smem slice ----
    {
        float sA, sB;
        up2(s2, sA, sB);
        float tA = rcp_fast(fmaxf(sA, 1e-24f));
        float tB = rcp_fast(fmaxf(sB, 1e-24f));
        u64 T = pk2(tA, tB);
        float* soA = s_out + (wid * RPW + lane) * NPAIR;
        float* soB = soA + 32 * NPAIR;
        #pragma unroll
        for (int p = 0; p < NPAIR; p++) {
            u64 u = f2mul(m2[p], T);
            float uA, uB;
            up2(u, uA, uB);
            soA[p] = sqrt_fast(uA);
            soB[p] = sqrt_fast(uB);
        }
    }
    __syncwarp();

    // ---- warp-private coalesced float4 writeback (64 rows = 960 floats) ----
    if (!GUARD) {
        // full block: 240 float4 per warp, fully unrolled (7 rounds + half)
        float4* og = reinterpret_cast<float4*>(out + (size_t)wbase * NPAIR);
        const float4* sg = reinterpret_cast<const float4*>(s_out + wid * RPW * NPAIR);
        #pragma unroll
        for (int k = 0; k < 7; k++)
            og[lane + 32 * k] = sg[lane + 32 * k];
        if (lane < 16)
            og[224 + lane] = sg[224 + lane];
    } else {
        int rows_here = B - wbase;
        if (rows_here > 0) {
            if (rows_here > RPW) rows_here = RPW;
            const int total = rows_here * NPAIR;
            const int nvec = total >> 2;
            float4* og = reinterpret_cast<float4*>(out + (size_t)wbase * NPAIR);
            const float* ss = s_out + wid * RPW * NPAIR;
            const float4* sg = reinterpret_cast<const float4*>(ss);
            for (int v = lane; v < nvec; v += 32)
                og[v] = sg[v];
            for (int e = (nvec << 2) + lane; e < total; e += 32)
                out[(size_t)wbase * NPAIR + e] = ss[e];
        }
    }
}

extern "C" void kernel_launch(void* const* d_in, const int* in_sizes, int n_in,
                              void* d_out, int out_size)
{
    const float* x    = (const float*)d_in[0];
    const float* pphi = (const float*)d_in[1];
    const float* pth  = (const float*)d_in[2];
    const float* kin  = (const float*)d_in[3];
    const float* bin  = (const float*)d_in[4];
    float* out = (float*)d_out;

    int B = in_sizes[0] / 12;
    int blocks = (B + RPB - 1) / RPB;
    if (B % RPB == 0)
        bqnn_kernel<false><<<blocks, TPB>>>(x, pphi, pth, kin, bin, out, B);
    else
        bqnn_kernel<true><<<blocks, TPB>>>(x, pphi, pth, kin, bin, out, B);
}